// round 1
// baseline (speedup 1.0000x reference)
#include <cuda_runtime.h>
#include <cstdint>
#include <cmath>

// Problem constants
#define EMB    1024
#define DIN    2048      // 2*EMB (LSTM input width, also MLP width)
#define HDIM   2048      // H
#define G4     8192      // 4*H (gate width)
#define BB     1024      // batch
#define NSTEP  5
#define PATHL  11

// ---------------------------------------------------------------------------
// Scratch (device globals: allocation-free, graph-capture safe)
// ---------------------------------------------------------------------------
__device__ float g_X [NSTEP * BB * DIN];   // 40 MB  gathered LSTM inputs
__device__ float g_XW[NSTEP * BB * G4];    // 160 MB X @ W_lstm + b (all steps)
__device__ float g_Z [BB * G4];            // 32 MB  per-step gates
__device__ float g_h [BB * HDIM];          // 8 MB
__device__ float g_c [BB * HDIM];          // 8 MB
__device__ float g_A1[BB * DIN];           // 8 MB
__device__ float g_A2[BB * DIN];           // 8 MB

// ---------------------------------------------------------------------------
// Helpers
// ---------------------------------------------------------------------------
__device__ __forceinline__ uint32_t smem_u32(const void* p) {
    return (uint32_t)__cvta_generic_to_shared(p);
}

#define CP_ASYNC16(dst_u32, src_ptr)                                          \
    asm volatile("cp.async.cg.shared.global [%0], [%1], 16;\n"                \
                 :: "r"(dst_u32), "l"(src_ptr) : "memory")

#define CP_COMMIT()  asm volatile("cp.async.commit_group;\n" ::: "memory")
#define CP_WAIT(n)   asm volatile("cp.async.wait_group %0;\n" :: "n"(n) : "memory")

#define MMA_TF32(d, a, b)                                                     \
    asm volatile("mma.sync.aligned.m16n8k8.row.col.f32.tf32.tf32.f32 "        \
                 "{%0,%1,%2,%3}, {%4,%5,%6,%7}, {%8,%9}, {%0,%1,%2,%3};\n"    \
                 : "+f"((d)[0]), "+f"((d)[1]), "+f"((d)[2]), "+f"((d)[3])     \
                 : "r"((a)[0]), "r"((a)[1]), "r"((a)[2]), "r"((a)[3]),        \
                   "r"((b)[0]), "r"((b)[1]))

// ---------------------------------------------------------------------------
// 1) Gather: X[t*BB+b] = [emb[path[b,1+2t]], emb[path[b,2+2t]]]
// ---------------------------------------------------------------------------
__global__ void gather_kernel(const int* __restrict__ path,
                              const float* __restrict__ emb)
{
    int tb = blockIdx.x;            // 0..5119 = t*1024 + b
    int t  = tb >> 10;
    int b  = tb & 1023;
    int p1 = path[b * PATHL + 1 + 2 * t];
    int p2 = path[b * PATHL + 2 + 2 * t];
    const float4* s1 = (const float4*)(emb + (size_t)p1 * EMB);
    const float4* s2 = (const float4*)(emb + (size_t)p2 * EMB);
    float4* dst = (float4*)(g_X + (size_t)tb * DIN);
    for (int i = threadIdx.x; i < EMB / 4; i += blockDim.x) {
        dst[i]           = s1[i];
        dst[i + EMB / 4] = s2[i];
    }
}

// ---------------------------------------------------------------------------
// 2) TF32 GEMM: C[M,N] = A[M,K] @ B[K,N]  (+bias / +addmat / relu epilogues)
//    All row-major fp32. M%128==0, N%128==0, K%16==0.
//    mode 0: C = acc + bias[n]
//    mode 1: C = acc + addmat[m*N+n]
//    mode 2: C = relu(acc + bias[n])
// ---------------------------------------------------------------------------
#define BM 128
#define BN 128
#define BK 16
#define AS_STRIDE 20     // 16 + 4 pad  -> conflict-free A frag loads
#define BS_STRIDE 136    // 128 + 8 pad -> conflict-free B frag loads

__global__ __launch_bounds__(256)
void gemm_tf32(const float* __restrict__ A, const float* __restrict__ B,
               const float* __restrict__ bias, const float* __restrict__ addmat,
               float* __restrict__ C, int M, int N, int K, int mode)
{
    __shared__ float As[2][BM * AS_STRIDE];
    __shared__ float Bs[2][BK * BS_STRIDE];

    const int tid  = threadIdx.x;
    const int bm   = blockIdx.y * BM;
    const int bn   = blockIdx.x * BN;
    const int warp = tid >> 5;
    const int lane = tid & 31;
    const int wm   = (warp & 1) * 64;   // 2 warps along M (64 rows each)
    const int wn   = (warp >> 1) * 32;  // 4 warps along N (32 cols each)
    const int lg   = lane >> 2;         // groupID 0..7
    const int lt   = lane & 3;          // threadID_in_group 0..3

    // per-thread global->shared coords (256 threads, 2 float4 each per matrix)
    const int a_row = tid >> 2;   // 0..63 (+64)
    const int a_c4  = tid & 3;    // float4 col within BK=16
    const int b_row = tid >> 5;   // 0..7 (+8)
    const int b_c4  = tid & 31;   // float4 col within BN=128

    const uint32_t as_base0 = smem_u32(&As[0][0]);
    const uint32_t as_base1 = smem_u32(&As[1][0]);
    const uint32_t bs_base0 = smem_u32(&Bs[0][0]);
    const uint32_t bs_base1 = smem_u32(&Bs[1][0]);

    float acc[4][4][4];
    #pragma unroll
    for (int i = 0; i < 4; i++)
        #pragma unroll
        for (int j = 0; j < 4; j++)
            #pragma unroll
            for (int r = 0; r < 4; r++) acc[i][j][r] = 0.0f;

    auto load_tile = [&](int buf, int k0) {
        uint32_t ab = buf ? as_base1 : as_base0;
        uint32_t bb = buf ? bs_base1 : bs_base0;
        #pragma unroll
        for (int s = 0; s < 2; s++) {
            int row = a_row + s * 64;
            uint32_t d = ab + (uint32_t)(row * AS_STRIDE + a_c4 * 4) * 4u;
            const float* src = A + (size_t)(bm + row) * K + k0 + a_c4 * 4;
            CP_ASYNC16(d, src);
        }
        #pragma unroll
        for (int s = 0; s < 2; s++) {
            int row = b_row + s * 8;
            uint32_t d = bb + (uint32_t)(row * BS_STRIDE + b_c4 * 4) * 4u;
            const float* src = B + (size_t)(k0 + row) * N + bn + b_c4 * 4;
            CP_ASYNC16(d, src);
        }
    };

    const int NT = K / BK;
    load_tile(0, 0);
    CP_COMMIT();

    for (int kt = 0; kt < NT; kt++) {
        const int buf = kt & 1;
        if (kt + 1 < NT) {
            load_tile(buf ^ 1, (kt + 1) * BK);
            CP_COMMIT();
            CP_WAIT(1);
        } else {
            CP_WAIT(0);
        }
        __syncthreads();

        const float* Asb = As[buf];
        const float* Bsb = Bs[buf];
        #pragma unroll
        for (int kk = 0; kk < BK; kk += 8) {
            uint32_t afr[4][4];
            uint32_t bfr[4][2];
            #pragma unroll
            for (int i = 0; i < 4; i++) {
                int r0 = wm + i * 16 + lg;
                int cc = kk + lt;
                afr[i][0] = __float_as_uint(Asb[r0 * AS_STRIDE + cc]);
                afr[i][1] = __float_as_uint(Asb[(r0 + 8) * AS_STRIDE + cc]);
                afr[i][2] = __float_as_uint(Asb[r0 * AS_STRIDE + cc + 4]);
                afr[i][3] = __float_as_uint(Asb[(r0 + 8) * AS_STRIDE + cc + 4]);
            }
            #pragma unroll
            for (int j = 0; j < 4; j++) {
                int cc = wn + j * 8 + lg;
                int rr = kk + lt;
                bfr[j][0] = __float_as_uint(Bsb[rr * BS_STRIDE + cc]);
                bfr[j][1] = __float_as_uint(Bsb[(rr + 4) * BS_STRIDE + cc]);
            }
            #pragma unroll
            for (int i = 0; i < 4; i++)
                #pragma unroll
                for (int j = 0; j < 4; j++)
                    MMA_TF32(acc[i][j], afr[i], bfr[j]);
        }
        __syncthreads();
    }

    // Epilogue
    #pragma unroll
    for (int i = 0; i < 4; i++) {
        #pragma unroll
        for (int j = 0; j < 4; j++) {
            int r0 = bm + wm + i * 16 + lg;
            int c0 = bn + wn + j * 8 + lt * 2;
            #pragma unroll
            for (int q = 0; q < 4; q++) {
                int r = r0 + (q >> 1) * 8;
                int c = c0 + (q & 1);
                float v = acc[i][j][q];
                if (mode == 0) {
                    v += bias[c];
                } else if (mode == 1) {
                    v += addmat[(size_t)r * N + c];
                } else {
                    v = fmaxf(v + bias[c], 0.0f);
                }
                C[(size_t)r * N + c] = v;
            }
        }
    }
}

// ---------------------------------------------------------------------------
// 3) LSTM cell: gates from Z (B x 4H), update c,h. first=1 => c_prev = 0.
// ---------------------------------------------------------------------------
__global__ void lstm_cell(const float* __restrict__ Z, int first)
{
    int idx = blockIdx.x * blockDim.x + threadIdx.x;
    if (idx >= BB * HDIM) return;
    int b = idx >> 11;       // /2048
    int j = idx & 2047;
    const float* zr = Z + (size_t)b * G4;
    float zi = zr[j];
    float zf = zr[j + HDIM];
    float zg = zr[j + 2 * HDIM];
    float zo = zr[j + 3 * HDIM];
    float ig = 1.0f / (1.0f + expf(-zi));
    float fg = 1.0f / (1.0f + expf(-zf));
    float gg = tanhf(zg);
    float og = 1.0f / (1.0f + expf(-zo));
    float cp = first ? 0.0f : g_c[idx];
    float cn = fg * cp + ig * gg;
    g_c[idx] = cn;
    g_h[idx] = og * tanhf(cn);
}

// ---------------------------------------------------------------------------
// 4) Head: logits = A2 @ W3 + b3 (N=2), softmax -> out
// ---------------------------------------------------------------------------
__global__ void head_kernel(const float* __restrict__ W3,
                            const float* __restrict__ b3,
                            float* __restrict__ out)
{
    int b = blockIdx.x;
    const float* a = g_A2 + (size_t)b * DIN;
    float p0 = 0.0f, p1 = 0.0f;
    for (int k = threadIdx.x; k < DIN; k += blockDim.x) {
        float av = a[k];
        p0 += av * W3[k * 2 + 0];
        p1 += av * W3[k * 2 + 1];
    }
    #pragma unroll
    for (int o = 16; o > 0; o >>= 1) {
        p0 += __shfl_down_sync(0xFFFFFFFFu, p0, o);
        p1 += __shfl_down_sync(0xFFFFFFFFu, p1, o);
    }
    __shared__ float r0[8], r1[8];
    int warp = threadIdx.x >> 5, lane = threadIdx.x & 31;
    if (lane == 0) { r0[warp] = p0; r1[warp] = p1; }
    __syncthreads();
    if (threadIdx.x == 0) {
        float l0 = b3[0], l1 = b3[1];
        #pragma unroll
        for (int w = 0; w < 8; w++) { l0 += r0[w]; l1 += r1[w]; }
        float m = fmaxf(l0, l1);
        float e0 = expf(l0 - m), e1 = expf(l1 - m);
        float inv = 1.0f / (e0 + e1);
        out[b * 2 + 0] = e0 * inv;
        out[b * 2 + 1] = e1 * inv;
    }
}

// ---------------------------------------------------------------------------
// Launch
// ---------------------------------------------------------------------------
extern "C" void kernel_launch(void* const* d_in, const int* in_sizes, int n_in,
                              void* d_out, int out_size)
{
    (void)in_sizes; (void)n_in; (void)out_size;
    const int*   path   = (const int*)  d_in[0];
    const float* emb    = (const float*)d_in[1];
    const float* W_lstm = (const float*)d_in[2];
    const float* U_lstm = (const float*)d_in[3];
    const float* b_lstm = (const float*)d_in[4];
    const float* W1     = (const float*)d_in[5];
    const float* b1     = (const float*)d_in[6];
    const float* W2     = (const float*)d_in[7];
    const float* b2     = (const float*)d_in[8];
    const float* W3     = (const float*)d_in[9];
    const float* b3     = (const float*)d_in[10];
    float* out = (float*)d_out;

    float *X, *XW, *Z;
    cudaGetSymbolAddress((void**)&X,  g_X);
    cudaGetSymbolAddress((void**)&XW, g_XW);
    cudaGetSymbolAddress((void**)&Z,  g_Z);
    float *h, *A1, *A2;
    cudaGetSymbolAddress((void**)&h,  g_h);
    cudaGetSymbolAddress((void**)&A1, g_A1);
    cudaGetSymbolAddress((void**)&A2, g_A2);

    // 1) gather inputs for all 5 steps
    gather_kernel<<<NSTEP * BB, 256>>>(path, emb);

    // 2) XW = X @ W_lstm + b_lstm  (M=5120, N=8192, K=2048)
    {
        dim3 g(G4 / BN, (NSTEP * BB) / BM);
        gemm_tf32<<<g, 256>>>(X, W_lstm, b_lstm, nullptr, XW,
                              NSTEP * BB, G4, DIN, 0);
    }

    // 3) step 0: h=0 => Z = XW[0]; run cell directly on XW slice
    lstm_cell<<<(BB * HDIM) / 256, 256>>>(XW, 1);

    // 4) steps 1..4: Z = h @ U_lstm + XW[t]; then cell
    for (int t = 1; t < NSTEP; t++) {
        dim3 g(G4 / BN, BB / BM);
        gemm_tf32<<<g, 256>>>(h, U_lstm, nullptr, XW + (size_t)t * BB * G4, Z,
                              BB, G4, HDIM, 1);
        lstm_cell<<<(BB * HDIM) / 256, 256>>>(Z, 0);
    }

    // 5) MLP: A1 = relu(h@W1+b1); A2 = relu(A1@W2+b2)
    {
        dim3 g(DIN / BN, BB / BM);
        gemm_tf32<<<g, 256>>>(h,  W1, b1, nullptr, A1, BB, DIN, HDIM, 2);
        gemm_tf32<<<g, 256>>>(A1, W2, b2, nullptr, A2, BB, DIN, DIN, 2);
    }

    // 6) head + softmax
    head_kernel<<<BB, 256>>>(W3, b3, out);
}

// round 3
// speedup vs baseline: 1.2830x; 1.2830x over previous
#include <cuda_runtime.h>
#include <cstdint>
#include <cmath>

// Problem constants
#define EMB    1024
#define DIN    2048      // 2*EMB
#define HDIM   2048      // H
#define G4     8192      // 4*H
#define BB     1024      // batch
#define NSTEP  5
#define PATHL  11

// ---------------------------------------------------------------------------
// Scratch (device globals: allocation-free, graph-capture safe)
// ---------------------------------------------------------------------------
__device__ float g_X [NSTEP * BB * DIN];   // gathered LSTM inputs
__device__ float g_XW[NSTEP * BB * G4];    // X @ W_lstm + b (all steps)
__device__ float g_Z [BB * G4];
__device__ float g_h [BB * HDIM];
__device__ float g_c [BB * HDIM];
__device__ float g_A1[BB * DIN];
__device__ float g_A2[BB * DIN];

// ---------------------------------------------------------------------------
// Helpers
// ---------------------------------------------------------------------------
__device__ __forceinline__ uint32_t smem_u32(const void* p) {
    return (uint32_t)__cvta_generic_to_shared(p);
}

#define CP_ASYNC16(dst_u32, src_ptr)                                          \
    asm volatile("cp.async.cg.shared.global [%0], [%1], 16;\n"                \
                 :: "r"(dst_u32), "l"(src_ptr) : "memory")
#define CP_COMMIT()  asm volatile("cp.async.commit_group;\n" ::: "memory")
#define CP_WAIT(n)   asm volatile("cp.async.wait_group %0;\n" :: "n"(n) : "memory")

#define MMA_TF32(d, a, b)                                                     \
    asm volatile("mma.sync.aligned.m16n8k8.row.col.f32.tf32.tf32.f32 "        \
                 "{%0,%1,%2,%3}, {%4,%5,%6,%7}, {%8,%9}, {%0,%1,%2,%3};\n"    \
                 : "+f"((d)[0]), "+f"((d)[1]), "+f"((d)[2]), "+f"((d)[3])     \
                 : "r"((a)[0]), "r"((a)[1]), "r"((a)[2]), "r"((a)[3]),        \
                   "r"((b)[0]), "r"((b)[1]))

// ---------------------------------------------------------------------------
// 1) Gather: X[t*BB+b] = [emb[path[b,1+2t]], emb[path[b,2+2t]]]
// ---------------------------------------------------------------------------
__global__ void gather_kernel(const int* __restrict__ path,
                              const float* __restrict__ emb)
{
    int tb = blockIdx.x;            // t*1024 + b
    int t  = tb >> 10;
    int b  = tb & 1023;
    int p1 = path[b * PATHL + 1 + 2 * t];
    int p2 = path[b * PATHL + 2 + 2 * t];
    const float4* s1 = (const float4*)(emb + (size_t)p1 * EMB);
    const float4* s2 = (const float4*)(emb + (size_t)p2 * EMB);
    float4* dst = (float4*)(g_X + (size_t)tb * DIN);
    for (int i = threadIdx.x; i < EMB / 4; i += blockDim.x) {
        dst[i]           = s1[i];
        dst[i + EMB / 4] = s2[i];
    }
}

// ---------------------------------------------------------------------------
// 2) TF32 GEMM: C[M,N] = A[M,K] @ B[K,N] (+ epilogue)
//    mode 0: +bias[n]   mode 1: +addmat[m,n]   mode 2: relu(+bias[n])
//    M%128==0, N%128==0, K%64==0. 256 threads, 8 warps (2M x 4N), warp 64x32.
//    3-stage cp.async ring, BK=32, double-buffered register fragments.
// ---------------------------------------------------------------------------
#define BM 128
#define BN 128
#define BK 32
#define STAGES 3
#define AST 36            // A smem row stride (floats): conflict-free frag LDS
#define BST 136           // B smem row stride (floats)
#define A_STAGE (BM * AST)    // 4608 floats
#define B_STAGE (BK * BST)    // 4352 floats
#define SMEM_FLOATS (STAGES * (A_STAGE + B_STAGE))
#define SMEM_BYTES  (SMEM_FLOATS * 4)   // 107,520 B

__global__ __launch_bounds__(256, 2)
void gemm_tf32(const float* __restrict__ A, const float* __restrict__ B,
               const float* __restrict__ bias, const float* __restrict__ addmat,
               float* __restrict__ C, int M, int N, int K, int mode)
{
    extern __shared__ float sm[];
    float* As = sm;
    float* Bs = sm + STAGES * A_STAGE;

    const int tid  = threadIdx.x;
    const int warp = tid >> 5;
    const int lane = tid & 31;
    const int wm   = (warp & 1) * 64;
    const int wn   = (warp >> 1) * 32;
    const int lg   = lane >> 2;
    const int lt   = lane & 3;
    const int bm   = blockIdx.y * BM;
    const int bn   = blockIdx.x * BN;

    // global->smem coords: A 128x32 (4 x float4/thread), B 32x128 (4 x float4)
    const int ar = tid >> 2;            // 0..63 (+64)
    const int ac = (tid & 3) * 4;       // 0,4,8,12 (+16)
    const int br = tid >> 3;            // 0..31
    const int bc = (tid & 7) * 4;       // 0..28 (+32,+64,+96)

    const float* gA = A + (size_t)(bm + ar) * K + ac;
    const float* gB = B + (size_t)br * N + bn + bc;
    const uint32_t sAu = smem_u32(As);
    const uint32_t sBu = smem_u32(Bs);

    auto load_stage = [&](int slot, int k0) {
        uint32_t ab = sAu + (uint32_t)slot * (A_STAGE * 4);
        uint32_t bb = sBu + (uint32_t)slot * (B_STAGE * 4);
        const float* a0 = gA + k0;
        const float* b0 = gB + (size_t)k0 * N;
        #pragma unroll
        for (int s = 0; s < 2; s++)
            #pragma unroll
            for (int c = 0; c < 2; c++)
                CP_ASYNC16(ab + (uint32_t)((ar + s * 64) * AST + ac + c * 16) * 4u,
                           a0 + (size_t)s * 64 * K + c * 16);
        #pragma unroll
        for (int c = 0; c < 4; c++)
            CP_ASYNC16(bb + (uint32_t)(br * BST + bc + c * 32) * 4u,
                       b0 + c * 32);
    };

    uint32_t afr[2][4][4];
    uint32_t bfr[2][4][2];

    auto load_frags = [&](uint32_t (*af)[4], uint32_t (*bf)[2],
                          const float* sA, const float* sB, int kk) {
        #pragma unroll
        for (int i = 0; i < 4; i++) {
            const float* p = sA + (wm + i * 16 + lg) * AST + kk + lt;
            af[i][0] = __float_as_uint(p[0]);
            af[i][1] = __float_as_uint(p[8 * AST]);
            af[i][2] = __float_as_uint(p[4]);
            af[i][3] = __float_as_uint(p[8 * AST + 4]);
        }
        #pragma unroll
        for (int j = 0; j < 4; j++) {
            const float* p = sB + (kk + lt) * BST + wn + j * 8 + lg;
            bf[j][0] = __float_as_uint(p[0]);
            bf[j][1] = __float_as_uint(p[4 * BST]);
        }
    };

    float acc[4][4][4];
    #pragma unroll
    for (int i = 0; i < 4; i++)
        #pragma unroll
        for (int j = 0; j < 4; j++)
            #pragma unroll
            for (int q = 0; q < 4; q++) acc[i][j][q] = 0.0f;

    const int NT = K / BK;   // >= 2 for all our shapes

    load_stage(0, 0);  CP_COMMIT();
    load_stage(1, BK); CP_COMMIT();
    CP_WAIT(1);
    __syncthreads();
    load_frags(afr[0], bfr[0], As, Bs, 0);

    for (int kt = 0; kt < NT; kt++) {
        if (kt + 2 < NT) load_stage((kt + 2) % STAGES, (kt + 2) * BK);
        CP_COMMIT();
        const float* cA = As + (kt % STAGES) * A_STAGE;
        const float* cB = Bs + (kt % STAGES) * B_STAGE;
        #pragma unroll
        for (int kk = 0; kk < 4; kk++) {
            const int cur = kk & 1;
            const int nxt = cur ^ 1;
            if (kk < 3) {
                load_frags(afr[nxt], bfr[nxt], cA, cB, (kk + 1) * 8);
            } else if (kt + 1 < NT) {
                CP_WAIT(1);          // stage kt+1 resident
                __syncthreads();     // everyone done reading slot kt
                const float* nA = As + ((kt + 1) % STAGES) * A_STAGE;
                const float* nB = Bs + ((kt + 1) % STAGES) * B_STAGE;
                load_frags(afr[nxt], bfr[nxt], nA, nB, 0);
            }
            #pragma unroll
            for (int i = 0; i < 4; i++)
                #pragma unroll
                for (int j = 0; j < 4; j++)
                    MMA_TF32(acc[i][j], afr[cur][i], bfr[cur][j]);
        }
    }

    // Epilogue: float2 stores (cols c0,c0+1 are adjacent)
    #pragma unroll
    for (int i = 0; i < 4; i++) {
        #pragma unroll
        for (int j = 0; j < 4; j++) {
            const int r0 = bm + wm + i * 16 + lg;
            const int c0 = bn + wn + j * 8 + lt * 2;
            #pragma unroll
            for (int h = 0; h < 2; h++) {        // rows r0, r0+8
                const int r = r0 + h * 8;
                float vx = acc[i][j][h * 2 + 0];
                float vy = acc[i][j][h * 2 + 1];
                if (mode == 0) {
                    vx += bias[c0]; vy += bias[c0 + 1];
                } else if (mode == 1) {
                    const float2 av = *(const float2*)(addmat + (size_t)r * N + c0);
                    vx += av.x; vy += av.y;
                } else {
                    vx = fmaxf(vx + bias[c0],     0.0f);
                    vy = fmaxf(vy + bias[c0 + 1], 0.0f);
                }
                *(float2*)(C + (size_t)r * N + c0) = make_float2(vx, vy);
            }
        }
    }
}

// ---------------------------------------------------------------------------
// 3) LSTM cell
// ---------------------------------------------------------------------------
__global__ void lstm_cell(const float* __restrict__ Z, int first)
{
    int idx = blockIdx.x * blockDim.x + threadIdx.x;
    if (idx >= BB * HDIM) return;
    int b = idx >> 11;
    int j = idx & 2047;
    const float* zr = Z + (size_t)b * G4;
    float zi = zr[j];
    float zf = zr[j + HDIM];
    float zg = zr[j + 2 * HDIM];
    float zo = zr[j + 3 * HDIM];
    float ig = 1.0f / (1.0f + expf(-zi));
    float fg = 1.0f / (1.0f + expf(-zf));
    float gg = tanhf(zg);
    float og = 1.0f / (1.0f + expf(-zo));
    float cp = first ? 0.0f : g_c[idx];
    float cn = fg * cp + ig * gg;
    g_c[idx] = cn;
    g_h[idx] = og * tanhf(cn);
}

// ---------------------------------------------------------------------------
// 4) Head: logits = A2 @ W3 + b3 (N=2), softmax
// ---------------------------------------------------------------------------
__global__ void head_kernel(const float* __restrict__ W3,
                            const float* __restrict__ b3,
                            float* __restrict__ out)
{
    int b = blockIdx.x;
    const float* a = g_A2 + (size_t)b * DIN;
    float p0 = 0.0f, p1 = 0.0f;
    for (int k = threadIdx.x; k < DIN; k += blockDim.x) {
        float av = a[k];
        p0 += av * W3[k * 2 + 0];
        p1 += av * W3[k * 2 + 1];
    }
    #pragma unroll
    for (int o = 16; o > 0; o >>= 1) {
        p0 += __shfl_down_sync(0xFFFFFFFFu, p0, o);
        p1 += __shfl_down_sync(0xFFFFFFFFu, p1, o);
    }
    __shared__ float r0[8], r1[8];
    int warp = threadIdx.x >> 5, lane = threadIdx.x & 31;
    if (lane == 0) { r0[warp] = p0; r1[warp] = p1; }
    __syncthreads();
    if (threadIdx.x == 0) {
        float l0 = b3[0], l1 = b3[1];
        #pragma unroll
        for (int w = 0; w < 8; w++) { l0 += r0[w]; l1 += r1[w]; }
        float m = fmaxf(l0, l1);
        float e0 = expf(l0 - m), e1 = expf(l1 - m);
        float inv = 1.0f / (e0 + e1);
        out[b * 2 + 0] = e0 * inv;
        out[b * 2 + 1] = e1 * inv;
    }
}

// ---------------------------------------------------------------------------
// Launch
// ---------------------------------------------------------------------------
extern "C" void kernel_launch(void* const* d_in, const int* in_sizes, int n_in,
                              void* d_out, int out_size)
{
    (void)in_sizes; (void)n_in; (void)out_size;
    const int*   path   = (const int*)  d_in[0];
    const float* emb    = (const float*)d_in[1];
    const float* W_lstm = (const float*)d_in[2];
    const float* U_lstm = (const float*)d_in[3];
    const float* b_lstm = (const float*)d_in[4];
    const float* W1     = (const float*)d_in[5];
    const float* b1     = (const float*)d_in[6];
    const float* W2     = (const float*)d_in[7];
    const float* b2     = (const float*)d_in[8];
    const float* W3     = (const float*)d_in[9];
    const float* b3     = (const float*)d_in[10];
    float* out = (float*)d_out;

    float *X, *XW, *Z, *h, *A1, *A2;
    cudaGetSymbolAddress((void**)&X,  g_X);
    cudaGetSymbolAddress((void**)&XW, g_XW);
    cudaGetSymbolAddress((void**)&Z,  g_Z);
    cudaGetSymbolAddress((void**)&h,  g_h);
    cudaGetSymbolAddress((void**)&A1, g_A1);
    cudaGetSymbolAddress((void**)&A2, g_A2);

    cudaFuncSetAttribute(gemm_tf32, cudaFuncAttributeMaxDynamicSharedMemorySize,
                         SMEM_BYTES);

    // 1) gather inputs for all 5 steps
    gather_kernel<<<NSTEP * BB, 256>>>(path, emb);

    // 2) XW = X @ W_lstm + b_lstm  (M=5120, N=8192, K=2048)
    gemm_tf32<<<dim3(G4 / BN, (NSTEP * BB) / BM), 256, SMEM_BYTES>>>(
        X, W_lstm, b_lstm, nullptr, XW, NSTEP * BB, G4, DIN, 0);

    // 3) step 0 (h=0): cell directly on XW[0]
    lstm_cell<<<(BB * HDIM) / 256, 256>>>(XW, 1);

    // 4) steps 1..4: Z = h @ U_lstm + XW[t]; cell
    for (int t = 1; t < NSTEP; t++) {
        gemm_tf32<<<dim3(G4 / BN, BB / BM), 256, SMEM_BYTES>>>(
            h, U_lstm, nullptr, XW + (size_t)t * BB * G4, Z, BB, G4, HDIM, 1);
        lstm_cell<<<(BB * HDIM) / 256, 256>>>(Z, 0);
    }

    // 5) MLP
    gemm_tf32<<<dim3(DIN / BN, BB / BM), 256, SMEM_BYTES>>>(
        h,  W1, b1, nullptr, A1, BB, DIN, HDIM, 2);
    gemm_tf32<<<dim3(DIN / BN, BB / BM), 256, SMEM_BYTES>>>(
        A1, W2, b2, nullptr, A2, BB, DIN, DIN, 2);

    // 6) head + softmax
    head_kernel<<<BB, 256>>>(W3, b3, out);
}